// round 3
// baseline (speedup 1.0000x reference)
#include <cuda_runtime.h>
#include <cuda_bf16.h>
#include <mma.h>
#include <cstdint>

#define BATCH 512
#define TT 365
#define DD 256
#define TP 384
#define NSTEPS 16

// ---------------- scratch (device globals; no allocation allowed) ----------------
__device__ float g_x0[BATCH * 608];
__device__ float g_ct1[BATCH * 512];
__device__ float g_ct2[BATCH * 384];
__device__ float g_state[BATCH * 512];                      // [h | c]
__device__ float g_encproj[(size_t)TT * BATCH * 128];       // enc @ Wa1[:256]  (tf32)
__device__ float g_sproj[BATCH * 128];
__device__ float g_scores[BATCH * TP];
__device__ float g_w[BATCH * TP];
__device__ float g_xh[BATCH * 512];                         // [inp | h]
__device__ float g_gates[BATCH * 1024];
__device__ float g_Wg[512 * 1024];                          // [Wih^T ; Whh^T]
__device__ float g_bg[1024];
__device__ float g_outs[NSTEPS * BATCH * 256];
__device__ float g_td1[NSTEPS * BATCH * 128];

__device__ __forceinline__ float sigf(float x) { return 1.0f / (1.0f + expf(-x)); }

// ---------------- generic fp32 SGEMM: C = act(A[MxK] @ W[KxN] + bias) ----------------
// Requires: M%64==0, N%64==0, K%16==0. Block 256 thr, tile 64x64x16,
// each thread computes a 4x4 micro-tile.
template <int ACT>
__global__ void sgemm(const float* __restrict__ A, const float* __restrict__ W,
                      const float* __restrict__ bias, float* __restrict__ C,
                      int M, int N, int K) {
    __shared__ float As[16][68];
    __shared__ float Bs[16][64];
    const int tid = threadIdx.x;
    const int m0 = blockIdx.y * 64;
    const int n0 = blockIdx.x * 64;
    const int tx = tid & 15;
    const int ty = tid >> 4;
    const int am = tid >> 2;         // 0..63
    const int ak = (tid & 3) * 4;    // 0,4,8,12
    const int bk = tid >> 4;         // 0..15
    const int bn = (tid & 15) * 4;   // 0..60

    float acc[4][4];
#pragma unroll
    for (int i = 0; i < 4; i++)
#pragma unroll
        for (int j = 0; j < 4; j++) acc[i][j] = 0.0f;

    for (int k0 = 0; k0 < K; k0 += 16) {
        float4 av = *reinterpret_cast<const float4*>(A + (size_t)(m0 + am) * K + k0 + ak);
        As[ak + 0][am] = av.x;
        As[ak + 1][am] = av.y;
        As[ak + 2][am] = av.z;
        As[ak + 3][am] = av.w;
        *reinterpret_cast<float4*>(&Bs[bk][bn]) =
            *reinterpret_cast<const float4*>(W + (size_t)(k0 + bk) * N + n0 + bn);
        __syncthreads();
#pragma unroll
        for (int kk = 0; kk < 16; kk++) {
            float4 a = *reinterpret_cast<const float4*>(&As[kk][ty * 4]);
            float4 b = *reinterpret_cast<const float4*>(&Bs[kk][tx * 4]);
            float aa[4] = {a.x, a.y, a.z, a.w};
            float bb[4] = {b.x, b.y, b.z, b.w};
#pragma unroll
            for (int i = 0; i < 4; i++)
#pragma unroll
                for (int j = 0; j < 4; j++) acc[i][j] += aa[i] * bb[j];
        }
        __syncthreads();
    }
#pragma unroll
    for (int i = 0; i < 4; i++) {
        const int m = m0 + ty * 4 + i;
#pragma unroll
        for (int j = 0; j < 4; j++) {
            const int n = n0 + tx * 4 + j;
            float v = acc[i][j] + (bias ? bias[n] : 0.0f);
            if (ACT) v = fmaxf(v, 0.0f);
            C[(size_t)m * N + n] = v;
        }
    }
}

// ---------------- build combined LSTM weight [Wih^T ; Whh^T] and bias ----------------
__global__ void prep_Wg(const float* __restrict__ Wih, const float* __restrict__ Whh,
                        const float* __restrict__ bih, const float* __restrict__ bhh) {
    int idx = blockIdx.x * blockDim.x + threadIdx.x;
    if (idx < 512 * 1024) {
        int k = idx >> 10;
        int n = idx & 1023;
        g_Wg[idx] = (k < 256) ? Wih[n * 256 + k] : Whh[n * 256 + (k - 256)];
    }
    if (idx < 1024) g_bg[idx] = bih[idx] + bhh[idx];
}

// ---------------- concat [e0|e1|e2|h|c] -> x0 [B,608] ----------------
// x_cat_static may be int32 (JAX default, x64 disabled) or int64. Detect at
// runtime: int64 little-endian with small values => every odd 32-bit word is 0.
__device__ __forceinline__ int cat_idx(const int* raw, int is64, int flat_idx) {
    return is64 ? raw[2 * flat_idx] : raw[flat_idx];
}

__global__ void build_x0(const int* __restrict__ xcat_raw, const float* __restrict__ sh,
                         const float* __restrict__ sc, const float* __restrict__ es,
                         const float* __restrict__ ei, const float* __restrict__ ef) {
    __shared__ int s_is64;
    int b = blockIdx.x;
    int t = threadIdx.x;  // 608 threads
    if (t == 0) {
        int is64 = 1;
        for (int i = 0; i < 32; i++)
            if (xcat_raw[2 * i + 1] != 0) { is64 = 0; break; }
        s_is64 = is64;
    }
    __syncthreads();
    const int is64 = s_is64;
    float v;
    if (t < 16) {
        int i0 = cat_idx(xcat_raw, is64, b * 3 + 0);
        i0 = min(max(i0, 0), 53);
        v = es[(size_t)i0 * 16 + t];
    } else if (t < 80) {
        int i1 = cat_idx(xcat_raw, is64, b * 3 + 1);
        i1 = min(max(i1, 0), 4035);
        v = ei[(size_t)i1 * 64 + (t - 16)];
    } else if (t < 96) {
        int i2 = cat_idx(xcat_raw, is64, b * 3 + 2);
        i2 = min(max(i2, 0), 32);
        v = ef[(size_t)i2 * 16 + (t - 80)];
    } else if (t < 352) {
        v = sh[b * 256 + (t - 96)];
    } else {
        v = sc[b * 256 + (t - 352)];
    }
    g_x0[b * 608 + t] = v;
}

// ---------------- enc_proj = enc @ Wa1[:256], tf32 WMMA (fp32 accum) ----------------
__global__ void encproj_kernel(const float* __restrict__ enc, const float* __restrict__ Wa1) {
    using namespace nvcuda;
    const int warp = threadIdx.x >> 5;        // 0..7 -> n tile
    const size_t m0 = (size_t)blockIdx.x * 16;
    const int n0 = warp * 16;
    wmma::fragment<wmma::accumulator, 16, 16, 8, float> acc;
    wmma::fill_fragment(acc, 0.0f);
#pragma unroll
    for (int k = 0; k < 256; k += 8) {
        wmma::fragment<wmma::matrix_a, 16, 16, 8, wmma::precision::tf32, wmma::row_major> fa;
        wmma::fragment<wmma::matrix_b, 16, 16, 8, wmma::precision::tf32, wmma::row_major> fb;
        wmma::load_matrix_sync(fa, enc + m0 * 256 + k, 256);
        wmma::load_matrix_sync(fb, Wa1 + (size_t)k * 128 + n0, 128);
#pragma unroll
        for (int i = 0; i < fa.num_elements; i++) fa.x[i] = wmma::__float_to_tf32(fa.x[i]);
#pragma unroll
        for (int i = 0; i < fb.num_elements; i++) fb.x[i] = wmma::__float_to_tf32(fb.x[i]);
        wmma::mma_sync(acc, fa, fb, acc);
    }
    wmma::store_matrix_sync(g_encproj + m0 * 128 + n0, acc, 128, wmma::mem_row_major);
}

// ---------------- scores: one warp per (t,b); ba2 dropped (softmax-invariant) ----------------
__global__ void scores_kernel(const float* __restrict__ Wa2) {
    const int gw = (blockIdx.x * blockDim.x + threadIdx.x) >> 5;  // 0..T*B-1
    const int lane = threadIdx.x & 31;
    const int t = gw / BATCH;
    const int b = gw - t * BATCH;
    float4 e = reinterpret_cast<const float4*>(g_encproj + (size_t)gw * 128)[lane];
    float4 s = reinterpret_cast<const float4*>(g_sproj + b * 128)[lane];
    float4 w = reinterpret_cast<const float4*>(Wa2)[lane];
    float acc = fmaxf(e.x + s.x, 0.0f) * w.x + fmaxf(e.y + s.y, 0.0f) * w.y +
                fmaxf(e.z + s.z, 0.0f) * w.z + fmaxf(e.w + s.w, 0.0f) * w.w;
#pragma unroll
    for (int o = 16; o > 0; o >>= 1) acc += __shfl_down_sync(0xffffffff, acc, o);
    if (lane == 0) g_scores[b * TP + t] = acc;
}

// ---------------- softmax over t for each b ----------------
__global__ void softmax_kernel() {
    const int b = blockIdx.x;
    const int tid = threadIdx.x;  // 128
    __shared__ float red[128];
    float m = -1e30f;
    for (int t = tid; t < TT; t += 128) m = fmaxf(m, g_scores[b * TP + t]);
    red[tid] = m;
    __syncthreads();
    for (int s = 64; s > 0; s >>= 1) {
        if (tid < s) red[tid] = fmaxf(red[tid], red[tid + s]);
        __syncthreads();
    }
    m = red[0];
    __syncthreads();
    float sum = 0.0f;
    for (int t = tid; t < TT; t += 128) {
        float e = expf(g_scores[b * TP + t] - m);
        g_w[b * TP + t] = e;
        sum += e;
    }
    red[tid] = sum;
    __syncthreads();
    for (int s = 64; s > 0; s >>= 1) {
        if (tid < s) red[tid] += red[tid + s];
        __syncthreads();
    }
    float inv = 1.0f / red[0];
    for (int t = tid; t < TT; t += 128) g_w[b * TP + t] *= inv;
}

// ---------------- inp = sum_t w[t,b]*enc[t,b,:] (fp32 enc); also xh = [inp | h] ----------------
__global__ void wsum_kernel(const float* __restrict__ enc) {
    const int b = blockIdx.x;
    const int d = threadIdx.x;  // 256
    __shared__ float sw[TT];
    for (int t = d; t < TT; t += 256) sw[t] = g_w[b * TP + t];
    __syncthreads();
    const float* base = enc + (size_t)b * DD + d;
    const size_t stride = (size_t)BATCH * DD;
    float a0 = 0.f, a1 = 0.f, a2 = 0.f, a3 = 0.f;
    int t = 0;
    for (; t < 364; t += 4) {
        a0 += sw[t + 0] * base[(size_t)(t + 0) * stride];
        a1 += sw[t + 1] * base[(size_t)(t + 1) * stride];
        a2 += sw[t + 2] * base[(size_t)(t + 2) * stride];
        a3 += sw[t + 3] * base[(size_t)(t + 3) * stride];
    }
    a0 += sw[364] * base[(size_t)364 * stride];
    g_xh[b * 512 + d] = (a0 + a1) + (a2 + a3);
    g_xh[b * 512 + 256 + d] = g_state[b * 512 + d];  // current h
}

// ---------------- LSTM cell update; stash h_new into g_outs[step] ----------------
__global__ void lstm_kernel(int step) {
    const int b = blockIdx.x;
    const int j = threadIdx.x;  // 256
    const float* gb = g_gates + (size_t)b * 1024;
    float gi = gb[j];
    float gf = gb[256 + j];
    float gg = gb[512 + j];
    float go = gb[768 + j];
    float c = g_state[b * 512 + 256 + j];
    float cn = sigf(gf) * c + sigf(gi) * tanhf(gg);
    float hn = sigf(go) * tanhf(cn);
    g_state[b * 512 + j] = hn;
    g_state[b * 512 + 256 + j] = cn;
    g_outs[(size_t)step * BATCH * 256 + b * 256 + j] = hn;
}

// ---------------- final: out[row] = td1[row] . Wt2 + bt2 ----------------
__global__ void td_out_kernel(const float* __restrict__ Wt2, const float* __restrict__ bt2,
                              float* __restrict__ out) {
    const int gw = (blockIdx.x * blockDim.x + threadIdx.x) >> 5;  // row, 0..8191
    const int lane = threadIdx.x & 31;
    float4 h = reinterpret_cast<const float4*>(g_td1 + (size_t)gw * 128)[lane];
    float4 w = reinterpret_cast<const float4*>(Wt2)[lane];
    float acc = h.x * w.x + h.y * w.y + h.z * w.z + h.w * w.w;
#pragma unroll
    for (int o = 16; o > 0; o >>= 1) acc += __shfl_down_sync(0xffffffff, acc, o);
    if (lane == 0) out[gw] = acc + bt2[0];
}

// ---------------- host orchestration ----------------
extern "C" void kernel_launch(void* const* d_in, const int* in_sizes, int n_in,
                              void* d_out, int out_size) {
    (void)in_sizes; (void)n_in; (void)out_size;
    const int*   xcat    = (const int*)d_in[0];   // int32 or int64; detected in-kernel
    const float* state_h = (const float*)d_in[1];
    const float* state_c = (const float*)d_in[2];
    const float* enc     = (const float*)d_in[3];
    const float* es      = (const float*)d_in[4];
    const float* ei      = (const float*)d_in[5];
    const float* ef      = (const float*)d_in[6];
    const float* Wc1 = (const float*)d_in[7];  const float* bc1 = (const float*)d_in[8];
    const float* Wc2 = (const float*)d_in[9];  const float* bc2 = (const float*)d_in[10];
    const float* Wc3 = (const float*)d_in[11]; const float* bc3 = (const float*)d_in[12];
    const float* Wa1 = (const float*)d_in[13]; const float* ba1 = (const float*)d_in[14];
    const float* Wa2 = (const float*)d_in[15]; // ba2 = d_in[16] unused (softmax-invariant)
    const float* Wt1 = (const float*)d_in[17]; const float* bt1 = (const float*)d_in[18];
    const float* Wt2 = (const float*)d_in[19]; const float* bt2 = (const float*)d_in[20];
    const float* Wih = (const float*)d_in[21]; const float* Whh = (const float*)d_in[22];
    const float* bih = (const float*)d_in[23]; const float* bhh = (const float*)d_in[24];
    float* out = (float*)d_out;

    float *p_x0, *p_ct1, *p_ct2, *p_state, *p_sproj, *p_xh, *p_gates, *p_Wg, *p_bg,
        *p_outs, *p_td1;
    cudaGetSymbolAddress((void**)&p_x0, g_x0);
    cudaGetSymbolAddress((void**)&p_ct1, g_ct1);
    cudaGetSymbolAddress((void**)&p_ct2, g_ct2);
    cudaGetSymbolAddress((void**)&p_state, g_state);
    cudaGetSymbolAddress((void**)&p_sproj, g_sproj);
    cudaGetSymbolAddress((void**)&p_xh, g_xh);
    cudaGetSymbolAddress((void**)&p_gates, g_gates);
    cudaGetSymbolAddress((void**)&p_Wg, g_Wg);
    cudaGetSymbolAddress((void**)&p_bg, g_bg);
    cudaGetSymbolAddress((void**)&p_outs, g_outs);
    cudaGetSymbolAddress((void**)&p_td1, g_td1);

    // --- precompute ---
    prep_Wg<<<2048, 256>>>(Wih, Whh, bih, bhh);
    build_x0<<<BATCH, 608>>>(xcat, state_h, state_c, es, ei, ef);
    sgemm<1><<<dim3(512 / 64, 512 / 64), 256>>>(p_x0, Wc1, bc1, p_ct1, 512, 512, 608);
    sgemm<1><<<dim3(384 / 64, 512 / 64), 256>>>(p_ct1, Wc2, bc2, p_ct2, 512, 384, 512);
    sgemm<0><<<dim3(512 / 64, 512 / 64), 256>>>(p_ct2, Wc3, bc3, p_state, 512, 512, 384);
    encproj_kernel<<<TT * BATCH / 16, 256>>>(enc, Wa1);

    // --- 16 decode steps ---
    for (int step = 0; step < NSTEPS; step++) {
        // s_proj = [h|c] @ Wa1[256:768] + ba1
        sgemm<0><<<dim3(2, 8), 256>>>(p_state, Wa1 + 256 * 128, ba1, p_sproj, 512, 128, 512);
        scores_kernel<<<TT * BATCH / 8, 256>>>(Wa2);
        softmax_kernel<<<BATCH, 128>>>();
        wsum_kernel<<<BATCH, 256>>>(enc);
        // gates = [inp|h] @ [Wih^T;Whh^T] + (bih+bhh)
        sgemm<0><<<dim3(1024 / 64, 512 / 64), 256>>>(p_xh, p_Wg, p_bg, p_gates, 512, 1024, 512);
        lstm_kernel<<<BATCH, 256>>>(step);
    }

    // --- time-distributed head over all 16 outputs at once ---
    sgemm<1><<<dim3(128 / 64, NSTEPS * BATCH / 64), 256>>>(p_outs, Wt1, bt1, p_td1,
                                                           NSTEPS * BATCH, 128, 256);
    td_out_kernel<<<NSTEPS * BATCH / 8, 256>>>(Wt2, bt2, out);
}

// round 4
// speedup vs baseline: 1.0028x; 1.0028x over previous
#include <cuda_runtime.h>
#include <cuda_bf16.h>
#include <mma.h>
#include <cstdint>

#define BATCH 512
#define TT 365
#define DD 256
#define TP 384
#define NSTEPS 16

// ---------------- scratch (device globals; no allocation allowed) ----------------
__device__ float g_x0[BATCH * 608];
__device__ float g_ct1[BATCH * 512];
__device__ float g_ct2[BATCH * 384];
__device__ float g_state[BATCH * 512];                      // [h | c]
__device__ float g_encproj[(size_t)TT * BATCH * 128];       // enc @ Wa1[:256]  (tf32)
__device__ float g_sproj[BATCH * 128];
__device__ float g_scores[BATCH * TP];
__device__ float g_w[BATCH * TP];
__device__ float g_xh[BATCH * 512];                         // [inp | h]
__device__ float g_gates[BATCH * 1024];
__device__ float g_Wg[512 * 1024];                          // [Wih^T ; Whh^T]
__device__ float g_bg[1024];
__device__ float g_outs[NSTEPS * BATCH * 256];
__device__ float g_td1[NSTEPS * BATCH * 128];

__device__ __forceinline__ float sigf(float x) { return 1.0f / (1.0f + expf(-x)); }

// ---------------- generic fp32 SGEMM: C = act(A[MxK] @ W[KxN] + bias) ----------------
// Requires: M%64==0, N%64==0, K%16==0. Block 256 thr, tile 64x64x16,
// each thread computes a 4x4 micro-tile.
template <int ACT>
__global__ void sgemm(const float* __restrict__ A, const float* __restrict__ W,
                      const float* __restrict__ bias, float* __restrict__ C,
                      int M, int N, int K) {
    __shared__ float As[16][68];
    __shared__ float Bs[16][64];
    const int tid = threadIdx.x;
    const int m0 = blockIdx.y * 64;
    const int n0 = blockIdx.x * 64;
    const int tx = tid & 15;
    const int ty = tid >> 4;
    const int am = tid >> 2;         // 0..63
    const int ak = (tid & 3) * 4;    // 0,4,8,12
    const int bk = tid >> 4;         // 0..15
    const int bn = (tid & 15) * 4;   // 0..60

    float acc[4][4];
#pragma unroll
    for (int i = 0; i < 4; i++)
#pragma unroll
        for (int j = 0; j < 4; j++) acc[i][j] = 0.0f;

    for (int k0 = 0; k0 < K; k0 += 16) {
        float4 av = *reinterpret_cast<const float4*>(A + (size_t)(m0 + am) * K + k0 + ak);
        As[ak + 0][am] = av.x;
        As[ak + 1][am] = av.y;
        As[ak + 2][am] = av.z;
        As[ak + 3][am] = av.w;
        *reinterpret_cast<float4*>(&Bs[bk][bn]) =
            *reinterpret_cast<const float4*>(W + (size_t)(k0 + bk) * N + n0 + bn);
        __syncthreads();
#pragma unroll
        for (int kk = 0; kk < 16; kk++) {
            float4 a = *reinterpret_cast<const float4*>(&As[kk][ty * 4]);
            float4 b = *reinterpret_cast<const float4*>(&Bs[kk][tx * 4]);
            float aa[4] = {a.x, a.y, a.z, a.w};
            float bb[4] = {b.x, b.y, b.z, b.w};
#pragma unroll
            for (int i = 0; i < 4; i++)
#pragma unroll
                for (int j = 0; j < 4; j++) acc[i][j] += aa[i] * bb[j];
        }
        __syncthreads();
    }
#pragma unroll
    for (int i = 0; i < 4; i++) {
        const int m = m0 + ty * 4 + i;
#pragma unroll
        for (int j = 0; j < 4; j++) {
            const int n = n0 + tx * 4 + j;
            float v = acc[i][j] + (bias ? bias[n] : 0.0f);
            if (ACT) v = fmaxf(v, 0.0f);
            C[(size_t)m * N + n] = v;
        }
    }
}

// ---------------- build combined LSTM weight [Wih^T ; Whh^T] and bias ----------------
__global__ void prep_Wg(const float* __restrict__ Wih, const float* __restrict__ Whh,
                        const float* __restrict__ bih, const float* __restrict__ bhh) {
    int idx = blockIdx.x * blockDim.x + threadIdx.x;
    if (idx < 512 * 1024) {
        int k = idx >> 10;
        int n = idx & 1023;
        g_Wg[idx] = (k < 256) ? Wih[n * 256 + k] : Whh[n * 256 + (k - 256)];
    }
    if (idx < 1024) g_bg[idx] = bih[idx] + bhh[idx];
}

// ---------------- concat [e0|e1|e2|h|c] -> x0 [B,608] ----------------
// x_cat_static may be int32 (JAX default, x64 disabled) or int64. Detect at
// runtime: int64 little-endian with small values => every odd 32-bit word is 0.
__device__ __forceinline__ int cat_idx(const int* raw, int is64, int flat_idx) {
    return is64 ? raw[2 * flat_idx] : raw[flat_idx];
}

__global__ void build_x0(const int* __restrict__ xcat_raw, const float* __restrict__ sh,
                         const float* __restrict__ sc, const float* __restrict__ es,
                         const float* __restrict__ ei, const float* __restrict__ ef) {
    __shared__ int s_is64;
    int b = blockIdx.x;
    int t = threadIdx.x;  // 608 threads
    if (t == 0) {
        int is64 = 1;
        for (int i = 0; i < 32; i++)
            if (xcat_raw[2 * i + 1] != 0) { is64 = 0; break; }
        s_is64 = is64;
    }
    __syncthreads();
    const int is64 = s_is64;
    float v;
    if (t < 16) {
        int i0 = cat_idx(xcat_raw, is64, b * 3 + 0);
        i0 = min(max(i0, 0), 53);
        v = es[(size_t)i0 * 16 + t];
    } else if (t < 80) {
        int i1 = cat_idx(xcat_raw, is64, b * 3 + 1);
        i1 = min(max(i1, 0), 4035);
        v = ei[(size_t)i1 * 64 + (t - 16)];
    } else if (t < 96) {
        int i2 = cat_idx(xcat_raw, is64, b * 3 + 2);
        i2 = min(max(i2, 0), 32);
        v = ef[(size_t)i2 * 16 + (t - 80)];
    } else if (t < 352) {
        v = sh[b * 256 + (t - 96)];
    } else {
        v = sc[b * 256 + (t - 352)];
    }
    g_x0[b * 608 + t] = v;
}

// ---------------- enc_proj = enc @ Wa1[:256], tf32 WMMA (fp32 accum) ----------------
__global__ void encproj_kernel(const float* __restrict__ enc, const float* __restrict__ Wa1) {
    using namespace nvcuda;
    const int warp = threadIdx.x >> 5;        // 0..7 -> n tile
    const size_t m0 = (size_t)blockIdx.x * 16;
    const int n0 = warp * 16;
    wmma::fragment<wmma::accumulator, 16, 16, 8, float> acc;
    wmma::fill_fragment(acc, 0.0f);
#pragma unroll
    for (int k = 0; k < 256; k += 8) {
        wmma::fragment<wmma::matrix_a, 16, 16, 8, wmma::precision::tf32, wmma::row_major> fa;
        wmma::fragment<wmma::matrix_b, 16, 16, 8, wmma::precision::tf32, wmma::row_major> fb;
        wmma::load_matrix_sync(fa, enc + m0 * 256 + k, 256);
        wmma::load_matrix_sync(fb, Wa1 + (size_t)k * 128 + n0, 128);
#pragma unroll
        for (int i = 0; i < fa.num_elements; i++) fa.x[i] = wmma::__float_to_tf32(fa.x[i]);
#pragma unroll
        for (int i = 0; i < fb.num_elements; i++) fb.x[i] = wmma::__float_to_tf32(fb.x[i]);
        wmma::mma_sync(acc, fa, fb, acc);
    }
    wmma::store_matrix_sync(g_encproj + m0 * 128 + n0, acc, 128, wmma::mem_row_major);
}

// ---------------- scores: one warp per (t,b); ba2 dropped (softmax-invariant) ----------------
__global__ void scores_kernel(const float* __restrict__ Wa2) {
    const int gw = (blockIdx.x * blockDim.x + threadIdx.x) >> 5;  // 0..T*B-1
    const int lane = threadIdx.x & 31;
    const int t = gw / BATCH;
    const int b = gw - t * BATCH;
    float4 e = reinterpret_cast<const float4*>(g_encproj + (size_t)gw * 128)[lane];
    float4 s = reinterpret_cast<const float4*>(g_sproj + b * 128)[lane];
    float4 w = reinterpret_cast<const float4*>(Wa2)[lane];
    float acc = fmaxf(e.x + s.x, 0.0f) * w.x + fmaxf(e.y + s.y, 0.0f) * w.y +
                fmaxf(e.z + s.z, 0.0f) * w.z + fmaxf(e.w + s.w, 0.0f) * w.w;
#pragma unroll
    for (int o = 16; o > 0; o >>= 1) acc += __shfl_down_sync(0xffffffff, acc, o);
    if (lane == 0) g_scores[b * TP + t] = acc;
}

// ---------------- softmax over t for each b ----------------
__global__ void softmax_kernel() {
    const int b = blockIdx.x;
    const int tid = threadIdx.x;  // 128
    __shared__ float red[128];
    float m = -1e30f;
    for (int t = tid; t < TT; t += 128) m = fmaxf(m, g_scores[b * TP + t]);
    red[tid] = m;
    __syncthreads();
    for (int s = 64; s > 0; s >>= 1) {
        if (tid < s) red[tid] = fmaxf(red[tid], red[tid + s]);
        __syncthreads();
    }
    m = red[0];
    __syncthreads();
    float sum = 0.0f;
    for (int t = tid; t < TT; t += 128) {
        float e = expf(g_scores[b * TP + t] - m);
        g_w[b * TP + t] = e;
        sum += e;
    }
    red[tid] = sum;
    __syncthreads();
    for (int s = 64; s > 0; s >>= 1) {
        if (tid < s) red[tid] += red[tid + s];
        __syncthreads();
    }
    float inv = 1.0f / red[0];
    for (int t = tid; t < TT; t += 128) g_w[b * TP + t] *= inv;
}

// ---------------- inp = sum_t w[t,b]*enc[t,b,:] (fp32 enc); also xh = [inp | h] ----------------
__global__ void wsum_kernel(const float* __restrict__ enc) {
    const int b = blockIdx.x;
    const int d = threadIdx.x;  // 256
    __shared__ float sw[TT];
    for (int t = d; t < TT; t += 256) sw[t] = g_w[b * TP + t];
    __syncthreads();
    const float* base = enc + (size_t)b * DD + d;
    const size_t stride = (size_t)BATCH * DD;
    float a0 = 0.f, a1 = 0.f, a2 = 0.f, a3 = 0.f;
    int t = 0;
    for (; t < 364; t += 4) {
        a0 += sw[t + 0] * base[(size_t)(t + 0) * stride];
        a1 += sw[t + 1] * base[(size_t)(t + 1) * stride];
        a2 += sw[t + 2] * base[(size_t)(t + 2) * stride];
        a3 += sw[t + 3] * base[(size_t)(t + 3) * stride];
    }
    a0 += sw[364] * base[(size_t)364 * stride];
    g_xh[b * 512 + d] = (a0 + a1) + (a2 + a3);
    g_xh[b * 512 + 256 + d] = g_state[b * 512 + d];  // current h
}

// ---------------- LSTM cell update; stash h_new into g_outs[step] ----------------
__global__ void lstm_kernel(int step) {
    const int b = blockIdx.x;
    const int j = threadIdx.x;  // 256
    const float* gb = g_gates + (size_t)b * 1024;
    float gi = gb[j];
    float gf = gb[256 + j];
    float gg = gb[512 + j];
    float go = gb[768 + j];
    float c = g_state[b * 512 + 256 + j];
    float cn = sigf(gf) * c + sigf(gi) * tanhf(gg);
    float hn = sigf(go) * tanhf(cn);
    g_state[b * 512 + j] = hn;
    g_state[b * 512 + 256 + j] = cn;
    g_outs[(size_t)step * BATCH * 256 + b * 256 + j] = hn;
}

// ---------------- final: out[row] = td1[row] . Wt2 + bt2 ----------------
__global__ void td_out_kernel(const float* __restrict__ Wt2, const float* __restrict__ bt2,
                              float* __restrict__ out) {
    const int gw = (blockIdx.x * blockDim.x + threadIdx.x) >> 5;  // row, 0..8191
    const int lane = threadIdx.x & 31;
    float4 h = reinterpret_cast<const float4*>(g_td1 + (size_t)gw * 128)[lane];
    float4 w = reinterpret_cast<const float4*>(Wt2)[lane];
    float acc = h.x * w.x + h.y * w.y + h.z * w.z + h.w * w.w;
#pragma unroll
    for (int o = 16; o > 0; o >>= 1) acc += __shfl_down_sync(0xffffffff, acc, o);
    if (lane == 0) out[gw] = acc + bt2[0];
}

// ---------------- host orchestration ----------------
extern "C" void kernel_launch(void* const* d_in, const int* in_sizes, int n_in,
                              void* d_out, int out_size) {
    (void)in_sizes; (void)n_in; (void)out_size;
    const int*   xcat    = (const int*)d_in[0];   // int32 or int64; detected in-kernel
    const float* state_h = (const float*)d_in[1];
    const float* state_c = (const float*)d_in[2];
    const float* enc     = (const float*)d_in[3];
    const float* es      = (const float*)d_in[4];
    const float* ei      = (const float*)d_in[5];
    const float* ef      = (const float*)d_in[6];
    const float* Wc1 = (const float*)d_in[7];  const float* bc1 = (const float*)d_in[8];
    const float* Wc2 = (const float*)d_in[9];  const float* bc2 = (const float*)d_in[10];
    const float* Wc3 = (const float*)d_in[11]; const float* bc3 = (const float*)d_in[12];
    const float* Wa1 = (const float*)d_in[13]; const float* ba1 = (const float*)d_in[14];
    const float* Wa2 = (const float*)d_in[15]; // ba2 = d_in[16] unused (softmax-invariant)
    const float* Wt1 = (const float*)d_in[17]; const float* bt1 = (const float*)d_in[18];
    const float* Wt2 = (const float*)d_in[19]; const float* bt2 = (const float*)d_in[20];
    const float* Wih = (const float*)d_in[21]; const float* Whh = (const float*)d_in[22];
    const float* bih = (const float*)d_in[23]; const float* bhh = (const float*)d_in[24];
    float* out = (float*)d_out;

    float *p_x0, *p_ct1, *p_ct2, *p_state, *p_sproj, *p_xh, *p_gates, *p_Wg, *p_bg,
        *p_outs, *p_td1;
    cudaGetSymbolAddress((void**)&p_x0, g_x0);
    cudaGetSymbolAddress((void**)&p_ct1, g_ct1);
    cudaGetSymbolAddress((void**)&p_ct2, g_ct2);
    cudaGetSymbolAddress((void**)&p_state, g_state);
    cudaGetSymbolAddress((void**)&p_sproj, g_sproj);
    cudaGetSymbolAddress((void**)&p_xh, g_xh);
    cudaGetSymbolAddress((void**)&p_gates, g_gates);
    cudaGetSymbolAddress((void**)&p_Wg, g_Wg);
    cudaGetSymbolAddress((void**)&p_bg, g_bg);
    cudaGetSymbolAddress((void**)&p_outs, g_outs);
    cudaGetSymbolAddress((void**)&p_td1, g_td1);

    // --- precompute ---
    prep_Wg<<<2048, 256>>>(Wih, Whh, bih, bhh);
    build_x0<<<BATCH, 608>>>(xcat, state_h, state_c, es, ei, ef);
    sgemm<1><<<dim3(512 / 64, 512 / 64), 256>>>(p_x0, Wc1, bc1, p_ct1, 512, 512, 608);
    sgemm<1><<<dim3(384 / 64, 512 / 64), 256>>>(p_ct1, Wc2, bc2, p_ct2, 512, 384, 512);
    sgemm<0><<<dim3(512 / 64, 512 / 64), 256>>>(p_ct2, Wc3, bc3, p_state, 512, 512, 384);
    encproj_kernel<<<TT * BATCH / 16, 256>>>(enc, Wa1);

    // --- 16 decode steps ---
    for (int step = 0; step < NSTEPS; step++) {
        // s_proj = [h|c] @ Wa1[256:768] + ba1
        sgemm<0><<<dim3(2, 8), 256>>>(p_state, Wa1 + 256 * 128, ba1, p_sproj, 512, 128, 512);
        scores_kernel<<<TT * BATCH / 8, 256>>>(Wa2);
        softmax_kernel<<<BATCH, 128>>>();
        wsum_kernel<<<BATCH, 256>>>(enc);
        // gates = [inp|h] @ [Wih^T;Whh^T] + (bih+bhh)
        sgemm<0><<<dim3(1024 / 64, 512 / 64), 256>>>(p_xh, p_Wg, p_bg, p_gates, 512, 1024, 512);
        lstm_kernel<<<BATCH, 256>>>(step);
    }

    // --- time-distributed head over all 16 outputs at once ---
    sgemm<1><<<dim3(128 / 64, NSTEPS * BATCH / 64), 256>>>(p_outs, Wt1, bt1, p_td1,
                                                           NSTEPS * BATCH, 128, 256);
    td_out_kernel<<<NSTEPS * BATCH / 8, 256>>>(Wt2, bt2, out);
}